// round 8
// baseline (speedup 1.0000x reference)
#include <cuda_runtime.h>
#include <cuda_bf16.h>
#include <cstdint>

// ====================== constants ======================
static constexpr int D       = 64;
static constexpr int K       = 512;
static constexpr int M_TILE  = 64;
static constexpr int THREADS = 512;   // 16 warps: 4 row-groups x 4 col-groups

// Padded smem rows: 72 bf16 = 144 bytes. Row step = 36 words == 4 (mod 32)
// -> ldmatrix 16B fetches from 8 consecutive rows hit distinct bank groups.
static constexpr int ROW_BYTES = 144;

// smem layout (bytes)
static constexpr int SMEM_A    = 0;                          // 64  * 144 = 9216
static constexpr int SMEM_B    = 9216;                       // 512 * 144 = 73728
static constexpr int SMEM_CSQ  = 82944;                      // 512 * 4   = 2048
static constexpr int SMEM_XSQ  = 84992;                      // 64 * 4    = 256
static constexpr int SMEM_RSUM = 85248;                      // 4 * 64 * 4 = 1024
static constexpr int SMEM_TOTAL = 86272;

// ====================== PTX helpers ======================
__device__ __forceinline__ uint32_t smem_u32(const void* p) {
    uint32_t a;
    asm("{ .reg .u64 t; cvta.to.shared.u64 t, %1; cvt.u32.u64 %0, t; }" : "=r"(a) : "l"(p));
    return a;
}

#define LDMATRIX_X4(r0, r1, r2, r3, addr) \
    asm volatile("ldmatrix.sync.aligned.m8n8.x4.shared.b16 {%0,%1,%2,%3}, [%4];" \
                 : "=r"(r0), "=r"(r1), "=r"(r2), "=r"(r3) : "r"(addr))

#define LDMATRIX_X2(r0, r1, addr) \
    asm volatile("ldmatrix.sync.aligned.m8n8.x2.shared.b16 {%0,%1}, [%2];" \
                 : "=r"(r0), "=r"(r1) : "r"(addr))

#define MMA_16816_BF16(c0, c1, c2, c3, a0, a1, a2, a3, b0, b1) \
    asm volatile("mma.sync.aligned.m16n8k16.row.col.f32.bf16.bf16.f32 " \
                 "{%0,%1,%2,%3}, {%4,%5,%6,%7}, {%8,%9}, {%0,%1,%2,%3};" \
                 : "+f"(c0), "+f"(c1), "+f"(c2), "+f"(c3) \
                 : "r"(a0), "r"(a1), "r"(a2), "r"(a3), "r"(b0), "r"(b1))

// ====================== device scratch ======================
__device__ __nv_bfloat16 g_c_bf16[K * D];  // centroids, bf16, row-major [K, D]
__device__ float         g_c_sq[K];        // ||c_k||^2, fp32 exact

// ====================== prep kernel: centroids -> bf16 + c_sq ======================
__global__ void prep_centroids_kernel(const float* __restrict__ c) {
    int k = blockIdx.x * blockDim.x + threadIdx.x;
    if (k >= K) return;
    const float4* g = reinterpret_cast<const float4*>(c + (size_t)k * D);
    uint4* dst = reinterpret_cast<uint4*>(g_c_bf16) + k * 8;  // 8 uint4 per 64-bf16 row
    float s = 0.0f;
#pragma unroll
    for (int i = 0; i < 8; i++) {
        float4 a = g[2 * i], b = g[2 * i + 1];
        s += a.x * a.x + a.y * a.y + a.z * a.z + a.w * a.w;
        s += b.x * b.x + b.y * b.y + b.z * b.z + b.w * b.w;
        __nv_bfloat162 p0 = __floats2bfloat162_rn(a.x, a.y);
        __nv_bfloat162 p1 = __floats2bfloat162_rn(a.z, a.w);
        __nv_bfloat162 p2 = __floats2bfloat162_rn(b.x, b.y);
        __nv_bfloat162 p3 = __floats2bfloat162_rn(b.z, b.w);
        uint4 v;
        v.x = *reinterpret_cast<uint32_t*>(&p0);
        v.y = *reinterpret_cast<uint32_t*>(&p1);
        v.z = *reinterpret_cast<uint32_t*>(&p2);
        v.w = *reinterpret_cast<uint32_t*>(&p3);
        dst[i] = v;
    }
    g_c_sq[k] = s;
}

// ====================== main kernel ======================
__global__ __launch_bounds__(THREADS, 1)
void cluster_q_kernel(const float* __restrict__ x, float* __restrict__ out) {
    extern __shared__ char smem[];
    const uint32_t sb = smem_u32(smem);
    const int tid  = threadIdx.x;
    const int wid  = tid >> 5;
    const int lane = tid & 31;
    const int row0 = blockIdx.x * M_TILE;

    // --- B: copy pre-converted bf16 centroids into padded smem rows ---
    {
        const uint4* bsrc = reinterpret_cast<const uint4*>(g_c_bf16);
        for (int cid = tid; cid < K * 8; cid += THREADS) {   // 4096 16B chunks
            int row = cid >> 3, c8 = cid & 7;
            *reinterpret_cast<uint4*>(smem + SMEM_B + row * ROW_BYTES + c8 * 16) = bsrc[cid];
        }
    }
    // --- A: load fp32 x tile, convert to bf16, padded rows (64*8 = 512 chunks) ---
    {
        int cid = tid;                                       // exactly one chunk per thread
        int row = cid >> 3, c8 = cid & 7;
        const float4* g = reinterpret_cast<const float4*>(x + (size_t)(row0 + row) * D + c8 * 8);
        float4 a = g[0], b = g[1];
        __nv_bfloat162 p0 = __floats2bfloat162_rn(a.x, a.y);
        __nv_bfloat162 p1 = __floats2bfloat162_rn(a.z, a.w);
        __nv_bfloat162 p2 = __floats2bfloat162_rn(b.x, b.y);
        __nv_bfloat162 p3 = __floats2bfloat162_rn(b.z, b.w);
        uint4 v;
        v.x = *reinterpret_cast<uint32_t*>(&p0);
        v.y = *reinterpret_cast<uint32_t*>(&p1);
        v.z = *reinterpret_cast<uint32_t*>(&p2);
        v.w = *reinterpret_cast<uint32_t*>(&p3);
        *reinterpret_cast<uint4*>(smem + SMEM_A + row * ROW_BYTES + c8 * 16) = v;
    }
    // --- c_sq into smem ---
    float* csq = reinterpret_cast<float*>(smem + SMEM_CSQ);
    if (tid < K) csq[tid] = g_c_sq[tid];
    // --- x_sq per row (exact fp32) ---
    float* xsq = reinterpret_cast<float*>(smem + SMEM_XSQ);
    if (tid < M_TILE) {
        const float4* g = reinterpret_cast<const float4*>(x + (size_t)(row0 + tid) * D);
        float s = 0.0f;
#pragma unroll
        for (int i = 0; i < 16; i++) {
            float4 v = g[i];
            s += v.x * v.x + v.y * v.y + v.z * v.z + v.w * v.w;
        }
        xsq[tid] = s;
    }
    __syncthreads();

    // --- warp tiling: wr in 0..3 (16 rows), wc in 0..3 (128 cols) ---
    const int wr = wid >> 2;
    const int wc = wid & 3;

    float acc[16][4];
#pragma unroll
    for (int nt = 0; nt < 16; nt++)
#pragma unroll
        for (int j = 0; j < 4; j++) acc[nt][j] = 0.0f;

    // A fragment address: row = wr*16 + lane%16, k-half = lane/16
    const uint32_t a_base = sb + SMEM_A + (wr * 16 + (lane & 15)) * ROW_BYTES + (lane >> 4) * 16;
    // B fragment address: row n = wc*128 + nt*8 + lane%8, k-half = (lane/8)&1
    const uint32_t b_base = sb + SMEM_B + (wc * 128 + (lane & 7)) * ROW_BYTES + ((lane >> 3) & 1) * 16;

#pragma unroll
    for (int kt = 0; kt < 4; kt++) {
        uint32_t a0, a1, a2, a3;
        LDMATRIX_X4(a0, a1, a2, a3, a_base + kt * 32);
#pragma unroll
        for (int nt = 0; nt < 16; nt++) {
            uint32_t b0, b1;
            LDMATRIX_X2(b0, b1, b_base + nt * 8 * ROW_BYTES + kt * 32);
            MMA_16816_BF16(acc[nt][0], acc[nt][1], acc[nt][2], acc[nt][3],
                           a0, a1, a2, a3, b0, b1);
        }
    }

    // --- Epilogue: q = 1/(1 + x^2 + c^2 - 2 cross), in-register ---
    const int r_lo = wr * 16 + (lane >> 2);
    const int r_hi = r_lo + 8;
    const float xr_lo = xsq[r_lo] + 1.0f;
    const float xr_hi = xsq[r_hi] + 1.0f;

    float s_lo = 0.0f, s_hi = 0.0f;
#pragma unroll
    for (int nt = 0; nt < 16; nt++) {
        const int c0 = wc * 128 + nt * 8 + (lane & 3) * 2;
        const float cs0 = csq[c0], cs1 = csq[c0 + 1];
        float q00 = __fdividef(1.0f, fmaf(-2.0f, acc[nt][0], xr_lo + cs0));
        float q01 = __fdividef(1.0f, fmaf(-2.0f, acc[nt][1], xr_lo + cs1));
        float q10 = __fdividef(1.0f, fmaf(-2.0f, acc[nt][2], xr_hi + cs0));
        float q11 = __fdividef(1.0f, fmaf(-2.0f, acc[nt][3], xr_hi + cs1));
        acc[nt][0] = q00; acc[nt][1] = q01; acc[nt][2] = q10; acc[nt][3] = q11;
        s_lo += q00 + q01;
        s_hi += q10 + q11;
    }
    // reduce over the 4 quad lanes (cols within this warp's 128)
    s_lo += __shfl_xor_sync(0xFFFFFFFFu, s_lo, 1);
    s_lo += __shfl_xor_sync(0xFFFFFFFFu, s_lo, 2);
    s_hi += __shfl_xor_sync(0xFFFFFFFFu, s_hi, 1);
    s_hi += __shfl_xor_sync(0xFFFFFFFFu, s_hi, 2);

    float* rsum = reinterpret_cast<float*>(smem + SMEM_RSUM);  // [4][64]
    if ((lane & 3) == 0) {
        rsum[wc * 64 + r_lo] = s_lo;
        rsum[wc * 64 + r_hi] = s_hi;
    }
    __syncthreads();

    const float inv_lo = __fdividef(1.0f,
        rsum[r_lo] + rsum[64 + r_lo] + rsum[128 + r_lo] + rsum[192 + r_lo]);
    const float inv_hi = __fdividef(1.0f,
        rsum[r_hi] + rsum[64 + r_hi] + rsum[128 + r_hi] + rsum[192 + r_hi]);

    // --- normalized stores straight from registers (float2, 8B aligned) ---
    float* out_lo = out + (size_t)(row0 + r_lo) * K;
    float* out_hi = out + (size_t)(row0 + r_hi) * K;
#pragma unroll
    for (int nt = 0; nt < 16; nt++) {
        const int c0 = wc * 128 + nt * 8 + (lane & 3) * 2;
        float2 v0 = make_float2(acc[nt][0] * inv_lo, acc[nt][1] * inv_lo);
        float2 v1 = make_float2(acc[nt][2] * inv_hi, acc[nt][3] * inv_hi);
        *reinterpret_cast<float2*>(out_lo + c0) = v0;
        *reinterpret_cast<float2*>(out_hi + c0) = v1;
    }
}

// ====================== launch ======================
extern "C" void kernel_launch(void* const* d_in, const int* in_sizes, int n_in,
                              void* d_out, int out_size) {
    const float* x = (const float*)d_in[0];      // [N, 64] fp32
    const float* c = (const float*)d_in[1];      // [512, 64] fp32
    float* out = (float*)d_out;                  // [N, 512] fp32
    int N = in_sizes[0] / D;

    prep_centroids_kernel<<<(K + 255) / 256, 256>>>(c);

    cudaFuncSetAttribute(cluster_q_kernel,
                         cudaFuncAttributeMaxDynamicSharedMemorySize, SMEM_TOTAL);
    cluster_q_kernel<<<N / M_TILE, THREADS, SMEM_TOTAL>>>(x, out);
}

// round 10
// speedup vs baseline: 1.6158x; 1.6158x over previous
#include <cuda_runtime.h>
#include <cuda_bf16.h>
#include <cstdint>

// ====================== constants ======================
static constexpr int D         = 64;
static constexpr int K         = 512;
static constexpr int TILE_ROWS = 64;    // rows per row-tile
static constexpr int ROW_TILES = 4;     // row-tiles per CTA (B loaded once)
static constexpr int THREADS   = 512;   // 16 warps: 2 row-groups x 8 col-groups

// Padded smem rows: 72 bf16 = 144 bytes. Row step = 36 words == 4 (mod 32)
// -> ldmatrix 16B fetches from 8 consecutive rows hit distinct bank groups.
static constexpr int ROW_BYTES = 144;

// smem layout (bytes)
static constexpr int SMEM_A    = 0;                          // 64  * 144 = 9216
static constexpr int SMEM_B    = 9216;                       // 512 * 144 = 73728
static constexpr int SMEM_CSQ  = 82944;                      // 512 * 4   = 2048
static constexpr int SMEM_XSQ  = 84992;                      // 64 * 4    = 256
static constexpr int SMEM_RSUM = 85248;                      // 8 * 64 * 4 = 2048
static constexpr int SMEM_INV  = 87296;                      // 64 * 4    = 256
static constexpr int SMEM_TOTAL = 87552;

// ====================== PTX helpers ======================
__device__ __forceinline__ uint32_t smem_u32(const void* p) {
    uint32_t a;
    asm("{ .reg .u64 t; cvta.to.shared.u64 t, %1; cvt.u32.u64 %0, t; }" : "=r"(a) : "l"(p));
    return a;
}

#define LDMATRIX_X4(r0, r1, r2, r3, addr) \
    asm volatile("ldmatrix.sync.aligned.m8n8.x4.shared.b16 {%0,%1,%2,%3}, [%4];" \
                 : "=r"(r0), "=r"(r1), "=r"(r2), "=r"(r3) : "r"(addr))

#define MMA_16816_BF16(c0, c1, c2, c3, a0, a1, a2, a3, b0, b1) \
    asm volatile("mma.sync.aligned.m16n8k16.row.col.f32.bf16.bf16.f32 " \
                 "{%0,%1,%2,%3}, {%4,%5,%6,%7}, {%8,%9}, {%0,%1,%2,%3};" \
                 : "+f"(c0), "+f"(c1), "+f"(c2), "+f"(c3) \
                 : "r"(a0), "r"(a1), "r"(a2), "r"(a3), "r"(b0), "r"(b1))

// ====================== device scratch ======================
__device__ __nv_bfloat16 g_c_bf16[K * D];  // centroids, bf16, row-major [K, D]
__device__ float         g_c_sq[K];        // ||c_k||^2, fp32 exact

// ====================== prep kernel: centroids -> bf16 + c_sq ======================
__global__ void prep_centroids_kernel(const float* __restrict__ c) {
    int k = blockIdx.x * blockDim.x + threadIdx.x;
    if (k >= K) return;
    const float4* g = reinterpret_cast<const float4*>(c + (size_t)k * D);
    uint4* dst = reinterpret_cast<uint4*>(g_c_bf16) + k * 8;  // 8 uint4 per 64-bf16 row
    float s = 0.0f;
#pragma unroll
    for (int i = 0; i < 8; i++) {
        float4 a = g[2 * i], b = g[2 * i + 1];
        s += a.x * a.x + a.y * a.y + a.z * a.z + a.w * a.w;
        s += b.x * b.x + b.y * b.y + b.z * b.z + b.w * b.w;
        __nv_bfloat162 p0 = __floats2bfloat162_rn(a.x, a.y);
        __nv_bfloat162 p1 = __floats2bfloat162_rn(a.z, a.w);
        __nv_bfloat162 p2 = __floats2bfloat162_rn(b.x, b.y);
        __nv_bfloat162 p3 = __floats2bfloat162_rn(b.z, b.w);
        uint4 v;
        v.x = *reinterpret_cast<uint32_t*>(&p0);
        v.y = *reinterpret_cast<uint32_t*>(&p1);
        v.z = *reinterpret_cast<uint32_t*>(&p2);
        v.w = *reinterpret_cast<uint32_t*>(&p3);
        dst[i] = v;
    }
    g_c_sq[k] = s;
}

// ====================== main kernel ======================
__global__ __launch_bounds__(THREADS, 1)
void cluster_q_kernel(const float* __restrict__ x, float* __restrict__ out) {
    extern __shared__ char smem[];
    const uint32_t sb = smem_u32(smem);
    const int tid  = threadIdx.x;
    const int wid  = tid >> 5;
    const int lane = tid & 31;
    const int base_row0 = blockIdx.x * (TILE_ROWS * ROW_TILES);

    // --- B: copy pre-converted bf16 centroids into padded smem rows (once) ---
    {
        const uint4* bsrc = reinterpret_cast<const uint4*>(g_c_bf16);
        for (int cid = tid; cid < K * 8; cid += THREADS) {   // 4096 16B chunks
            int row = cid >> 3, c8 = cid & 7;
            *reinterpret_cast<uint4*>(smem + SMEM_B + row * ROW_BYTES + c8 * 16) = bsrc[cid];
        }
    }
    // --- c_sq into smem (once; THREADS == K) ---
    float* csq = reinterpret_cast<float*>(smem + SMEM_CSQ);
    csq[tid] = g_c_sq[tid];

    float* xsq  = reinterpret_cast<float*>(smem + SMEM_XSQ);
    float* rsum = reinterpret_cast<float*>(smem + SMEM_RSUM);   // [8 col-groups][64 rows]
    float* invr = reinterpret_cast<float*>(smem + SMEM_INV);    // [64 rows]

    // --- warp tiling: wr in 0..1 (32 rows), wc in 0..7 (64 cols) ---
    const int wr = wid >> 3;
    const int wc = wid & 7;

    // A fragment address: row = wr*32 + mt*16 + lane%16, k-half = lane/16
    const uint32_t a_base = sb + SMEM_A + (wr * 32 + (lane & 15)) * ROW_BYTES + (lane >> 4) * 16;
    // B pair-x4 address: pair p covers n-tiles (2p, 2p+1):
    //   lanes 0-7:   n = wc*64 + p*16 + lane,      koff + 0   -> r0 (nt=2p,   b0)
    //   lanes 8-15:  same rows,                    koff + 16  -> r1 (nt=2p,   b1)
    //   lanes 16-23: n = wc*64 + p*16 + 8 + l,     koff + 0   -> r2 (nt=2p+1, b0)
    //   lanes 24-31: same rows,                    koff + 16  -> r3 (nt=2p+1, b1)
    const uint32_t b_base = sb + SMEM_B +
        (wc * 64 + (lane >> 4) * 8 + (lane & 7)) * ROW_BYTES + ((lane >> 3) & 1) * 16;

    const int a_row = tid >> 3;        // A-fill: one 16B chunk per thread
    const int a_c8  = tid & 7;

#pragma unroll 1
    for (int t = 0; t < ROW_TILES; t++) {
        const int row0 = base_row0 + t * TILE_ROWS;

        // --- A: load fp32 x tile, convert to bf16, fused x_sq via shfl ---
        {
            const float4* g = reinterpret_cast<const float4*>(
                x + (size_t)(row0 + a_row) * D + a_c8 * 8);
            float4 a = g[0], b = g[1];
            float s = a.x * a.x + a.y * a.y + a.z * a.z + a.w * a.w
                    + b.x * b.x + b.y * b.y + b.z * b.z + b.w * b.w;
            __nv_bfloat162 p0 = __floats2bfloat162_rn(a.x, a.y);
            __nv_bfloat162 p1 = __floats2bfloat162_rn(a.z, a.w);
            __nv_bfloat162 p2 = __floats2bfloat162_rn(b.x, b.y);
            __nv_bfloat162 p3 = __floats2bfloat162_rn(b.z, b.w);
            uint4 v;
            v.x = *reinterpret_cast<uint32_t*>(&p0);
            v.y = *reinterpret_cast<uint32_t*>(&p1);
            v.z = *reinterpret_cast<uint32_t*>(&p2);
            v.w = *reinterpret_cast<uint32_t*>(&p3);
            *reinterpret_cast<uint4*>(smem + SMEM_A + a_row * ROW_BYTES + a_c8 * 16) = v;
            // reduce squares over the 8 lanes sharing this row
            s += __shfl_xor_sync(0xFFFFFFFFu, s, 1);
            s += __shfl_xor_sync(0xFFFFFFFFu, s, 2);
            s += __shfl_xor_sync(0xFFFFFFFFu, s, 4);
            if ((lane & 7) == 0) xsq[a_row] = s;
        }
        __syncthreads();

        // --- MMA: 2 m-tiles x 8 n-tiles x 4 k-steps ---
        float acc[2][8][4];
#pragma unroll
        for (int mt = 0; mt < 2; mt++)
#pragma unroll
            for (int nt = 0; nt < 8; nt++)
#pragma unroll
                for (int j = 0; j < 4; j++) acc[mt][nt][j] = 0.0f;

#pragma unroll
        for (int kt = 0; kt < 4; kt++) {
            uint32_t aA[2][4];
#pragma unroll
            for (int mt = 0; mt < 2; mt++)
                LDMATRIX_X4(aA[mt][0], aA[mt][1], aA[mt][2], aA[mt][3],
                            a_base + mt * 16 * ROW_BYTES + kt * 32);
#pragma unroll
            for (int p = 0; p < 4; p++) {
                uint32_t b0, b1, b2, b3;
                LDMATRIX_X4(b0, b1, b2, b3, b_base + p * 16 * ROW_BYTES + kt * 32);
#pragma unroll
                for (int mt = 0; mt < 2; mt++) {
                    MMA_16816_BF16(acc[mt][2*p][0],   acc[mt][2*p][1],
                                   acc[mt][2*p][2],   acc[mt][2*p][3],
                                   aA[mt][0], aA[mt][1], aA[mt][2], aA[mt][3], b0, b1);
                    MMA_16816_BF16(acc[mt][2*p+1][0], acc[mt][2*p+1][1],
                                   acc[mt][2*p+1][2], acc[mt][2*p+1][3],
                                   aA[mt][0], aA[mt][1], aA[mt][2], aA[mt][3], b2, b3);
                }
            }
        }

        // --- Epilogue: q = 1/(1 + x^2 + c^2 - 2 cross), in-register ---
        // thread rows: wr*32 + mt*16 + (lane>>2) + h*8,  mt,h in {0,1}
        const int rb = wr * 32 + (lane >> 2);
        float xr[2][2], s_acc[2][2];
#pragma unroll
        for (int mt = 0; mt < 2; mt++)
#pragma unroll
            for (int h = 0; h < 2; h++) {
                xr[mt][h] = xsq[rb + mt * 16 + h * 8] + 1.0f;
                s_acc[mt][h] = 0.0f;
            }

#pragma unroll
        for (int nt = 0; nt < 8; nt++) {
            const int c0 = wc * 64 + nt * 8 + (lane & 3) * 2;
            const float cs0 = csq[c0], cs1 = csq[c0 + 1];
#pragma unroll
            for (int mt = 0; mt < 2; mt++) {
                float q0 = __fdividef(1.0f, fmaf(-2.0f, acc[mt][nt][0], xr[mt][0] + cs0));
                float q1 = __fdividef(1.0f, fmaf(-2.0f, acc[mt][nt][1], xr[mt][0] + cs1));
                float q2 = __fdividef(1.0f, fmaf(-2.0f, acc[mt][nt][2], xr[mt][1] + cs0));
                float q3 = __fdividef(1.0f, fmaf(-2.0f, acc[mt][nt][3], xr[mt][1] + cs1));
                acc[mt][nt][0] = q0; acc[mt][nt][1] = q1;
                acc[mt][nt][2] = q2; acc[mt][nt][3] = q3;
                s_acc[mt][0] += q0 + q1;
                s_acc[mt][1] += q2 + q3;
            }
        }
        // reduce over the 4 quad lanes (cols within this warp's 64)
#pragma unroll
        for (int mt = 0; mt < 2; mt++)
#pragma unroll
            for (int h = 0; h < 2; h++) {
                s_acc[mt][h] += __shfl_xor_sync(0xFFFFFFFFu, s_acc[mt][h], 1);
                s_acc[mt][h] += __shfl_xor_sync(0xFFFFFFFFu, s_acc[mt][h], 2);
            }
        if ((lane & 3) == 0) {
#pragma unroll
            for (int mt = 0; mt < 2; mt++)
#pragma unroll
                for (int h = 0; h < 2; h++)
                    rsum[wc * 64 + rb + mt * 16 + h * 8] = s_acc[mt][h];
        }
        __syncthreads();

        // row normalizers (threads 0..63), conflict-free [g][row] reads
        if (tid < TILE_ROWS) {
            float s = 0.0f;
#pragma unroll
            for (int g2 = 0; g2 < 8; g2++) s += rsum[g2 * 64 + tid];
            invr[tid] = __fdividef(1.0f, s);
        }
        __syncthreads();

        // --- normalized stores straight from registers (float2, 8B aligned) ---
#pragma unroll
        for (int mt = 0; mt < 2; mt++) {
            const int r0r = rb + mt * 16;
            const float inv0 = invr[r0r];
            const float inv1 = invr[r0r + 8];
            float* o0 = out + (size_t)(row0 + r0r) * K;
            float* o1 = out + (size_t)(row0 + r0r + 8) * K;
#pragma unroll
            for (int nt = 0; nt < 8; nt++) {
                const int c0 = wc * 64 + nt * 8 + (lane & 3) * 2;
                *reinterpret_cast<float2*>(o0 + c0) =
                    make_float2(acc[mt][nt][0] * inv0, acc[mt][nt][1] * inv0);
                *reinterpret_cast<float2*>(o1 + c0) =
                    make_float2(acc[mt][nt][2] * inv1, acc[mt][nt][3] * inv1);
            }
        }
        __syncthreads();   // protect A/xsq/rsum before next tile refill
    }
}

// ====================== launch ======================
extern "C" void kernel_launch(void* const* d_in, const int* in_sizes, int n_in,
                              void* d_out, int out_size) {
    const float* x = (const float*)d_in[0];      // [N, 64] fp32
    const float* c = (const float*)d_in[1];      // [512, 64] fp32
    float* out = (float*)d_out;                  // [N, 512] fp32
    int N = in_sizes[0] / D;

    prep_centroids_kernel<<<(K + 255) / 256, 256>>>(c);

    cudaFuncSetAttribute(cluster_q_kernel,
                         cudaFuncAttributeMaxDynamicSharedMemorySize, SMEM_TOTAL);
    cluster_q_kernel<<<N / (TILE_ROWS * ROW_TILES), THREADS, SMEM_TOTAL>>>(x, out);
}

// round 11
// speedup vs baseline: 2.0491x; 1.2682x over previous
#include <cuda_runtime.h>
#include <cuda_bf16.h>
#include <cstdint>

// ====================== constants ======================
static constexpr int D         = 64;
static constexpr int K         = 512;
static constexpr int TILE_ROWS = 64;    // rows per row-tile
static constexpr int ROW_TILES = 4;     // row-tiles per CTA (B loaded once)
static constexpr int THREADS   = 512;   // 16 warps: 2 row-groups x 8 col-groups

// Padded smem rows: 72 bf16 = 144 bytes. Row step = 36 words == 4 (mod 32)
// -> ldmatrix 16B fetches from 8 consecutive rows hit distinct bank groups.
static constexpr int ROW_BYTES = 144;

// smem layout (bytes)
static constexpr int SMEM_A    = 0;                          // 64  * 144 = 9216
static constexpr int SMEM_B    = 9216;                       // 512 * 144 = 73728
static constexpr int SMEM_CSQ  = 82944;                      // 512 * 4   = 2048
static constexpr int SMEM_XSQ  = 84992;                      // 64 * 4    = 256
static constexpr int SMEM_RSUM = 85248;                      // 8 * 64 * 4 = 2048
static constexpr int SMEM_TOTAL = 87296;

// ====================== PTX helpers ======================
__device__ __forceinline__ uint32_t smem_u32(const void* p) {
    uint32_t a;
    asm("{ .reg .u64 t; cvta.to.shared.u64 t, %1; cvt.u32.u64 %0, t; }" : "=r"(a) : "l"(p));
    return a;
}

#define LDMATRIX_X4(r0, r1, r2, r3, addr) \
    asm volatile("ldmatrix.sync.aligned.m8n8.x4.shared.b16 {%0,%1,%2,%3}, [%4];" \
                 : "=r"(r0), "=r"(r1), "=r"(r2), "=r"(r3) : "r"(addr))

#define MMA_16816_BF16(c0, c1, c2, c3, a0, a1, a2, a3, b0, b1) \
    asm volatile("mma.sync.aligned.m16n8k16.row.col.f32.bf16.bf16.f32 " \
                 "{%0,%1,%2,%3}, {%4,%5,%6,%7}, {%8,%9}, {%0,%1,%2,%3};" \
                 : "+f"(c0), "+f"(c1), "+f"(c2), "+f"(c3) \
                 : "r"(a0), "r"(a1), "r"(a2), "r"(a3), "r"(b0), "r"(b1))

// convert 8 fp32 (2 float4) -> 4 bf16x2 packed words
__device__ __forceinline__ uint4 pack_bf16x8(float4 a, float4 b) {
    __nv_bfloat162 p0 = __floats2bfloat162_rn(a.x, a.y);
    __nv_bfloat162 p1 = __floats2bfloat162_rn(a.z, a.w);
    __nv_bfloat162 p2 = __floats2bfloat162_rn(b.x, b.y);
    __nv_bfloat162 p3 = __floats2bfloat162_rn(b.z, b.w);
    uint4 v;
    v.x = *reinterpret_cast<uint32_t*>(&p0);
    v.y = *reinterpret_cast<uint32_t*>(&p1);
    v.z = *reinterpret_cast<uint32_t*>(&p2);
    v.w = *reinterpret_cast<uint32_t*>(&p3);
    return v;
}

// ====================== main kernel ======================
__global__ __launch_bounds__(THREADS, 1)
void cluster_q_kernel(const float* __restrict__ x, const float* __restrict__ cen,
                      float* __restrict__ out) {
    extern __shared__ char smem[];
    const uint32_t sb = smem_u32(smem);
    const int tid  = threadIdx.x;
    const int wid  = tid >> 5;
    const int lane = tid & 31;
    const int base_row0 = blockIdx.x * (TILE_ROWS * ROW_TILES);

    float* csq  = reinterpret_cast<float*>(smem + SMEM_CSQ);
    float* xsq  = reinterpret_cast<float*>(smem + SMEM_XSQ);
    float* rsum = reinterpret_cast<float*>(smem + SMEM_RSUM);   // [8 col-groups][64 rows]

    // --- B: load fp32 centroids, convert to bf16, padded rows; fused c_sq (shfl) ---
    {
        const int c8 = tid & 7;
#pragma unroll
        for (int i = 0; i < 8; i++) {
            const int row = (tid >> 3) + i * 64;
            const float4* g = reinterpret_cast<const float4*>(cen + (size_t)row * D + c8 * 8);
            float4 a = g[0], b = g[1];
            float s = a.x * a.x + a.y * a.y + a.z * a.z + a.w * a.w
                    + b.x * b.x + b.y * b.y + b.z * b.z + b.w * b.w;
            *reinterpret_cast<uint4*>(smem + SMEM_B + row * ROW_BYTES + c8 * 16) =
                pack_bf16x8(a, b);
            s += __shfl_xor_sync(0xFFFFFFFFu, s, 1);
            s += __shfl_xor_sync(0xFFFFFFFFu, s, 2);
            s += __shfl_xor_sync(0xFFFFFFFFu, s, 4);
            if ((lane & 7) == 0) csq[row] = s;
        }
    }

    // --- warp tiling: wr in 0..1 (32 rows), wc in 0..7 (64 cols) ---
    const int wr = wid >> 3;
    const int wc = wid & 7;

    // A fragment address: row = wr*32 + mt*16 + lane%16, k-half = lane/16
    const uint32_t a_base = sb + SMEM_A + (wr * 32 + (lane & 15)) * ROW_BYTES + (lane >> 4) * 16;
    // B pair-x4 address: pair p covers n-tiles (2p, 2p+1)
    const uint32_t b_base = sb + SMEM_B +
        (wc * 64 + (lane >> 4) * 8 + (lane & 7)) * ROW_BYTES + ((lane >> 3) & 1) * 16;

    const int a_row = tid >> 3;        // A-fill: one 16B chunk per thread
    const int a_c8  = tid & 7;

    // preload tile 0's x chunk
    float4 pa, pb;
    {
        const float4* g = reinterpret_cast<const float4*>(
            x + (size_t)(base_row0 + a_row) * D + a_c8 * 8);
        pa = g[0]; pb = g[1];
    }

#pragma unroll 1
    for (int t = 0; t < ROW_TILES; t++) {
        const int row0 = base_row0 + t * TILE_ROWS;

        // --- A: convert preloaded x, store to smem, fused x_sq via shfl ---
        {
            float s = pa.x * pa.x + pa.y * pa.y + pa.z * pa.z + pa.w * pa.w
                    + pb.x * pb.x + pb.y * pb.y + pb.z * pb.z + pb.w * pb.w;
            *reinterpret_cast<uint4*>(smem + SMEM_A + a_row * ROW_BYTES + a_c8 * 16) =
                pack_bf16x8(pa, pb);
            s += __shfl_xor_sync(0xFFFFFFFFu, s, 1);
            s += __shfl_xor_sync(0xFFFFFFFFu, s, 2);
            s += __shfl_xor_sync(0xFFFFFFFFu, s, 4);
            if ((lane & 7) == 0) xsq[a_row] = s;
        }
        __syncthreads();   // sync1: A/B/csq ready; prior-tile rsum reads done

        // --- MMA: 2 m-tiles x 8 n-tiles x 4 k-steps ---
        float acc[2][8][4];
#pragma unroll
        for (int mt = 0; mt < 2; mt++)
#pragma unroll
            for (int nt = 0; nt < 8; nt++)
#pragma unroll
                for (int j = 0; j < 4; j++) acc[mt][nt][j] = 0.0f;

#pragma unroll
        for (int kt = 0; kt < 4; kt++) {
            uint32_t aA[2][4];
#pragma unroll
            for (int mt = 0; mt < 2; mt++)
                LDMATRIX_X4(aA[mt][0], aA[mt][1], aA[mt][2], aA[mt][3],
                            a_base + mt * 16 * ROW_BYTES + kt * 32);
#pragma unroll
            for (int p = 0; p < 4; p++) {
                uint32_t b0, b1, b2, b3;
                LDMATRIX_X4(b0, b1, b2, b3, b_base + p * 16 * ROW_BYTES + kt * 32);
#pragma unroll
                for (int mt = 0; mt < 2; mt++) {
                    MMA_16816_BF16(acc[mt][2*p][0],   acc[mt][2*p][1],
                                   acc[mt][2*p][2],   acc[mt][2*p][3],
                                   aA[mt][0], aA[mt][1], aA[mt][2], aA[mt][3], b0, b1);
                    MMA_16816_BF16(acc[mt][2*p+1][0], acc[mt][2*p+1][1],
                                   acc[mt][2*p+1][2], acc[mt][2*p+1][3],
                                   aA[mt][0], aA[mt][1], aA[mt][2], aA[mt][3], b2, b3);
                }
            }
        }

        // --- preload next tile's x (overlaps epilogue latency) ---
        if (t + 1 < ROW_TILES) {
            const float4* g = reinterpret_cast<const float4*>(
                x + (size_t)(row0 + TILE_ROWS + a_row) * D + a_c8 * 8);
            pa = g[0]; pb = g[1];
        }

        // --- Epilogue: q = 1/(1 + x^2 + c^2 - 2 cross), in-register ---
        const int rb = wr * 32 + (lane >> 2);
        float xr[2][2], s_acc[2][2];
#pragma unroll
        for (int mt = 0; mt < 2; mt++)
#pragma unroll
            for (int h = 0; h < 2; h++) {
                xr[mt][h] = xsq[rb + mt * 16 + h * 8] + 1.0f;
                s_acc[mt][h] = 0.0f;
            }

#pragma unroll
        for (int nt = 0; nt < 8; nt++) {
            const int c0 = wc * 64 + nt * 8 + (lane & 3) * 2;
            const float cs0 = csq[c0], cs1 = csq[c0 + 1];
#pragma unroll
            for (int mt = 0; mt < 2; mt++) {
                float q0 = __fdividef(1.0f, fmaf(-2.0f, acc[mt][nt][0], xr[mt][0] + cs0));
                float q1 = __fdividef(1.0f, fmaf(-2.0f, acc[mt][nt][1], xr[mt][0] + cs1));
                float q2 = __fdividef(1.0f, fmaf(-2.0f, acc[mt][nt][2], xr[mt][1] + cs0));
                float q3 = __fdividef(1.0f, fmaf(-2.0f, acc[mt][nt][3], xr[mt][1] + cs1));
                acc[mt][nt][0] = q0; acc[mt][nt][1] = q1;
                acc[mt][nt][2] = q2; acc[mt][nt][3] = q3;
                s_acc[mt][0] += q0 + q1;
                s_acc[mt][1] += q2 + q3;
            }
        }
#pragma unroll
        for (int mt = 0; mt < 2; mt++)
#pragma unroll
            for (int h = 0; h < 2; h++) {
                s_acc[mt][h] += __shfl_xor_sync(0xFFFFFFFFu, s_acc[mt][h], 1);
                s_acc[mt][h] += __shfl_xor_sync(0xFFFFFFFFu, s_acc[mt][h], 2);
            }
        if ((lane & 3) == 0) {
#pragma unroll
            for (int mt = 0; mt < 2; mt++)
#pragma unroll
                for (int h = 0; h < 2; h++)
                    rsum[wc * 64 + rb + mt * 16 + h * 8] = s_acc[mt][h];
        }
        __syncthreads();   // sync2: rsum complete; all MMAs done (A refill safe)

        // --- warp-local normalizers: lane L owns row wr*32+L ---
        float srow = 0.0f;
#pragma unroll
        for (int g2 = 0; g2 < 8; g2++) srow += rsum[g2 * 64 + wr * 32 + lane];
        const float invl = __fdividef(1.0f, srow);

        // --- normalized stores straight from registers (float2, 8B aligned) ---
#pragma unroll
        for (int mt = 0; mt < 2; mt++) {
            const float inv0 = __shfl_sync(0xFFFFFFFFu, invl, (lane >> 2) + mt * 16);
            const float inv1 = __shfl_sync(0xFFFFFFFFu, invl, (lane >> 2) + mt * 16 + 8);
            const int r0r = rb + mt * 16;
            float* o0 = out + (size_t)(row0 + r0r) * K;
            float* o1 = out + (size_t)(row0 + r0r + 8) * K;
#pragma unroll
            for (int nt = 0; nt < 8; nt++) {
                const int c0 = wc * 64 + nt * 8 + (lane & 3) * 2;
                *reinterpret_cast<float2*>(o0 + c0) =
                    make_float2(acc[mt][nt][0] * inv0, acc[mt][nt][1] * inv0);
                *reinterpret_cast<float2*>(o1 + c0) =
                    make_float2(acc[mt][nt][2] * inv1, acc[mt][nt][3] * inv1);
            }
        }
    }
}

// ====================== launch ======================
extern "C" void kernel_launch(void* const* d_in, const int* in_sizes, int n_in,
                              void* d_out, int out_size) {
    const float* x = (const float*)d_in[0];      // [N, 64] fp32
    const float* c = (const float*)d_in[1];      // [512, 64] fp32
    float* out = (float*)d_out;                  // [N, 512] fp32
    int N = in_sizes[0] / D;

    cudaFuncSetAttribute(cluster_q_kernel,
                         cudaFuncAttributeMaxDynamicSharedMemorySize, SMEM_TOTAL);
    cluster_q_kernel<<<N / (TILE_ROWS * ROW_TILES), THREADS, SMEM_TOTAL>>>(x, c, out);
}

// round 13
// speedup vs baseline: 2.0744x; 1.0123x over previous
#include <cuda_runtime.h>
#include <cuda_bf16.h>
#include <cstdint>

// ====================== constants ======================
static constexpr int D         = 64;
static constexpr int K         = 512;
static constexpr int TILE_ROWS = 64;    // rows per row-tile
static constexpr int ROW_TILES = 4;     // row-tiles per CTA (B loaded once)
static constexpr int THREADS   = 512;   // 16 warps: 2 row-groups x 8 col-groups

// Padded smem rows: 72 bf16 = 144 bytes. Row step = 36 words == 4 (mod 32)
// -> ldmatrix 16B fetches from 8 consecutive rows hit distinct bank groups.
static constexpr int ROW_BYTES = 144;

// smem layout (bytes) — A/xsq/rsum double-buffered
static constexpr int SMEM_A0    = 0;                          // 64 * 144 = 9216
static constexpr int SMEM_A1    = 9216;
static constexpr int SMEM_B     = 18432;                      // 512 * 144 = 73728
static constexpr int SMEM_CSQ   = 92160;                      // 512 * 4   = 2048
static constexpr int SMEM_XSQ0  = 94208;                      // 64 * 4
static constexpr int SMEM_XSQ1  = 94464;
static constexpr int SMEM_RSUM0 = 94720;                      // 8 * 64 * 4 = 2048
static constexpr int SMEM_RSUM1 = 96768;
static constexpr int SMEM_TOTAL = 98816;

// ====================== PTX helpers ======================
__device__ __forceinline__ uint32_t smem_u32(const void* p) {
    uint32_t a;
    asm("{ .reg .u64 t; cvta.to.shared.u64 t, %1; cvt.u32.u64 %0, t; }" : "=r"(a) : "l"(p));
    return a;
}

#define LDMATRIX_X4(r0, r1, r2, r3, addr) \
    asm volatile("ldmatrix.sync.aligned.m8n8.x4.shared.b16 {%0,%1,%2,%3}, [%4];" \
                 : "=r"(r0), "=r"(r1), "=r"(r2), "=r"(r3) : "r"(addr))

#define MMA_16816_BF16(c0, c1, c2, c3, a0, a1, a2, a3, b0, b1) \
    asm volatile("mma.sync.aligned.m16n8k16.row.col.f32.bf16.bf16.f32 " \
                 "{%0,%1,%2,%3}, {%4,%5,%6,%7}, {%8,%9}, {%0,%1,%2,%3};" \
                 : "+f"(c0), "+f"(c1), "+f"(c2), "+f"(c3) \
                 : "r"(a0), "r"(a1), "r"(a2), "r"(a3), "r"(b0), "r"(b1))

// convert 8 fp32 (2 float4) -> 4 bf16x2 packed words
__device__ __forceinline__ uint4 pack_bf16x8(float4 a, float4 b) {
    __nv_bfloat162 p0 = __floats2bfloat162_rn(a.x, a.y);
    __nv_bfloat162 p1 = __floats2bfloat162_rn(a.z, a.w);
    __nv_bfloat162 p2 = __floats2bfloat162_rn(b.x, b.y);
    __nv_bfloat162 p3 = __floats2bfloat162_rn(b.z, b.w);
    uint4 v;
    v.x = *reinterpret_cast<uint32_t*>(&p0);
    v.y = *reinterpret_cast<uint32_t*>(&p1);
    v.z = *reinterpret_cast<uint32_t*>(&p2);
    v.w = *reinterpret_cast<uint32_t*>(&p3);
    return v;
}

// ====================== main kernel ======================
__global__ __launch_bounds__(THREADS, 1)
void cluster_q_kernel(const float* __restrict__ x, const float* __restrict__ cen,
                      float* __restrict__ out) {
    extern __shared__ char smem[];
    const uint32_t sb = smem_u32(smem);
    const int tid  = threadIdx.x;
    const int wid  = tid >> 5;
    const int lane = tid & 31;
    const int base_row0 = blockIdx.x * (TILE_ROWS * ROW_TILES);

    float* csq = reinterpret_cast<float*>(smem + SMEM_CSQ);

    const int a_row = tid >> 3;        // A-fill: one 16B chunk per thread
    const int a_c8  = tid & 7;

    // issue tile-0 x loads early (latency hides under B fill)
    float4 pa, pb;
    {
        const float4* g = reinterpret_cast<const float4*>(
            x + (size_t)(base_row0 + a_row) * D + a_c8 * 8);
        pa = g[0]; pb = g[1];
    }

    // --- B: load fp32 centroids, convert to bf16, padded rows; fused c_sq (shfl) ---
    {
        const int c8 = tid & 7;
#pragma unroll
        for (int i = 0; i < 8; i++) {
            const int row = (tid >> 3) + i * 64;
            const float4* g = reinterpret_cast<const float4*>(cen + (size_t)row * D + c8 * 8);
            float4 a = g[0], b = g[1];
            float s = a.x * a.x + a.y * a.y + a.z * a.z + a.w * a.w
                    + b.x * b.x + b.y * b.y + b.z * b.z + b.w * b.w;
            *reinterpret_cast<uint4*>(smem + SMEM_B + row * ROW_BYTES + c8 * 16) =
                pack_bf16x8(a, b);
            s += __shfl_xor_sync(0xFFFFFFFFu, s, 1);
            s += __shfl_xor_sync(0xFFFFFFFFu, s, 2);
            s += __shfl_xor_sync(0xFFFFFFFFu, s, 4);
            if ((lane & 7) == 0) csq[row] = s;
        }
    }

    // --- A tile 0 into buffer 0 (+ xsq0) ---
    {
        float s = pa.x * pa.x + pa.y * pa.y + pa.z * pa.z + pa.w * pa.w
                + pb.x * pb.x + pb.y * pb.y + pb.z * pb.z + pb.w * pb.w;
        *reinterpret_cast<uint4*>(smem + SMEM_A0 + a_row * ROW_BYTES + a_c8 * 16) =
            pack_bf16x8(pa, pb);
        s += __shfl_xor_sync(0xFFFFFFFFu, s, 1);
        s += __shfl_xor_sync(0xFFFFFFFFu, s, 2);
        s += __shfl_xor_sync(0xFFFFFFFFu, s, 4);
        if ((lane & 7) == 0)
            reinterpret_cast<float*>(smem + SMEM_XSQ0)[a_row] = s;
    }
    __syncthreads();   // B, csq, A0, xsq0 ready

    // --- warp tiling: wr in 0..1 (32 rows), wc in 0..7 (64 cols) ---
    const int wr = wid >> 3;
    const int wc = wid & 7;

    const uint32_t a_frag_off = (wr * 32 + (lane & 15)) * ROW_BYTES + (lane >> 4) * 16;
    const uint32_t b_base = sb + SMEM_B +
        (wc * 64 + (lane >> 4) * 8 + (lane & 7)) * ROW_BYTES + ((lane >> 3) & 1) * 16;

#pragma unroll 1
    for (int t = 0; t < ROW_TILES; t++) {
        const int cur = t & 1;
        const int row0 = base_row0 + t * TILE_ROWS;
        const uint32_t a_base = sb + (cur ? SMEM_A1 : SMEM_A0) + a_frag_off;
        float* xsq  = reinterpret_cast<float*>(smem + (cur ? SMEM_XSQ1 : SMEM_XSQ0));
        float* rsum = reinterpret_cast<float*>(smem + (cur ? SMEM_RSUM1 : SMEM_RSUM0));

        // --- MMA: 2 m-tiles x 8 n-tiles x 4 k-steps ---
        float acc[2][8][4];
#pragma unroll
        for (int mt = 0; mt < 2; mt++)
#pragma unroll
            for (int nt = 0; nt < 8; nt++)
#pragma unroll
                for (int j = 0; j < 4; j++) acc[mt][nt][j] = 0.0f;

#pragma unroll
        for (int kt = 0; kt < 4; kt++) {
            uint32_t aA[2][4];
#pragma unroll
            for (int mt = 0; mt < 2; mt++)
                LDMATRIX_X4(aA[mt][0], aA[mt][1], aA[mt][2], aA[mt][3],
                            a_base + mt * 16 * ROW_BYTES + kt * 32);
#pragma unroll
            for (int p = 0; p < 4; p++) {
                uint32_t b0, b1, b2, b3;
                LDMATRIX_X4(b0, b1, b2, b3, b_base + p * 16 * ROW_BYTES + kt * 32);
#pragma unroll
                for (int mt = 0; mt < 2; mt++) {
                    MMA_16816_BF16(acc[mt][2*p][0],   acc[mt][2*p][1],
                                   acc[mt][2*p][2],   acc[mt][2*p][3],
                                   aA[mt][0], aA[mt][1], aA[mt][2], aA[mt][3], b0, b1);
                    MMA_16816_BF16(acc[mt][2*p+1][0], acc[mt][2*p+1][1],
                                   acc[mt][2*p+1][2], acc[mt][2*p+1][3],
                                   aA[mt][0], aA[mt][1], aA[mt][2], aA[mt][3], b2, b3);
                }
            }
        }

        // --- fill NEXT tile's A into the alternate buffer (safe: that buffer's
        //     last readers finished before the barrier that ended tile t-1) ---
        if (t + 1 < ROW_TILES) {
            const float4* g = reinterpret_cast<const float4*>(
                x + (size_t)(row0 + TILE_ROWS + a_row) * D + a_c8 * 8);
            float4 na = g[0], nb = g[1];
            float s = na.x * na.x + na.y * na.y + na.z * na.z + na.w * na.w
                    + nb.x * nb.x + nb.y * nb.y + nb.z * nb.z + nb.w * nb.w;
            *reinterpret_cast<uint4*>(smem + (cur ? SMEM_A0 : SMEM_A1)
                                      + a_row * ROW_BYTES + a_c8 * 16) = pack_bf16x8(na, nb);
            s += __shfl_xor_sync(0xFFFFFFFFu, s, 1);
            s += __shfl_xor_sync(0xFFFFFFFFu, s, 2);
            s += __shfl_xor_sync(0xFFFFFFFFu, s, 4);
            if ((lane & 7) == 0)
                reinterpret_cast<float*>(smem + (cur ? SMEM_XSQ0 : SMEM_XSQ1))[a_row] = s;
        }

        // --- Epilogue: q = 1/(1 + x^2 + c^2 - 2 cross), paired reciprocals ---
        const int rb = wr * 32 + (lane >> 2);
        float xr[2][2], s_acc[2][2];
#pragma unroll
        for (int mt = 0; mt < 2; mt++)
#pragma unroll
            for (int h = 0; h < 2; h++) {
                xr[mt][h] = xsq[rb + mt * 16 + h * 8] + 1.0f;
                s_acc[mt][h] = 0.0f;
            }

#pragma unroll
        for (int nt = 0; nt < 8; nt++) {
            const int c0 = wc * 64 + nt * 8 + (lane & 3) * 2;
            const float cs0 = csq[c0], cs1 = csq[c0 + 1];
#pragma unroll
            for (int mt = 0; mt < 2; mt++) {
                float d0 = fmaf(-2.0f, acc[mt][nt][0], xr[mt][0] + cs0);
                float d1 = fmaf(-2.0f, acc[mt][nt][1], xr[mt][0] + cs1);
                float d2 = fmaf(-2.0f, acc[mt][nt][2], xr[mt][1] + cs0);
                float d3 = fmaf(-2.0f, acc[mt][nt][3], xr[mt][1] + cs1);
                float r01 = __fdividef(1.0f, d0 * d1);
                float r23 = __fdividef(1.0f, d2 * d3);
                float q0 = r01 * d1, q1 = r01 * d0;
                float q2 = r23 * d3, q3 = r23 * d2;
                acc[mt][nt][0] = q0; acc[mt][nt][1] = q1;
                acc[mt][nt][2] = q2; acc[mt][nt][3] = q3;
                s_acc[mt][0] += q0 + q1;
                s_acc[mt][1] += q2 + q3;
            }
        }
#pragma unroll
        for (int mt = 0; mt < 2; mt++)
#pragma unroll
            for (int h = 0; h < 2; h++) {
                s_acc[mt][h] += __shfl_xor_sync(0xFFFFFFFFu, s_acc[mt][h], 1);
                s_acc[mt][h] += __shfl_xor_sync(0xFFFFFFFFu, s_acc[mt][h], 2);
            }
        if ((lane & 3) == 0) {
#pragma unroll
            for (int mt = 0; mt < 2; mt++)
#pragma unroll
                for (int h = 0; h < 2; h++)
                    rsum[wc * 64 + rb + mt * 16 + h * 8] = s_acc[mt][h];
        }
        __syncthreads();   // rsum ready; next-A visible; buffer reuse safe

        // --- warp-local normalizers: lane L owns row wr*32+L ---
        float srow = 0.0f;
#pragma unroll
        for (int g2 = 0; g2 < 8; g2++) srow += rsum[g2 * 64 + wr * 32 + lane];
        const float invl = __fdividef(1.0f, srow);

        // --- normalized streaming stores (float2, 8B aligned) ---
#pragma unroll
        for (int mt = 0; mt < 2; mt++) {
            const float inv0 = __shfl_sync(0xFFFFFFFFu, invl, (lane >> 2) + mt * 16);
            const float inv1 = __shfl_sync(0xFFFFFFFFu, invl, (lane >> 2) + mt * 16 + 8);
            const int r0r = rb + mt * 16;
            float* o0 = out + (size_t)(row0 + r0r) * K;
            float* o1 = out + (size_t)(row0 + r0r + 8) * K;
#pragma unroll
            for (int nt = 0; nt < 8; nt++) {
                const int c0 = wc * 64 + nt * 8 + (lane & 3) * 2;
                __stcs(reinterpret_cast<float2*>(o0 + c0),
                       make_float2(acc[mt][nt][0] * inv0, acc[mt][nt][1] * inv0));
                __stcs(reinterpret_cast<float2*>(o1 + c0),
                       make_float2(acc[mt][nt][2] * inv1, acc[mt][nt][3] * inv1));
            }
        }
    }
}

// ====================== launch ======================
extern "C" void kernel_launch(void* const* d_in, const int* in_sizes, int n_in,
                              void* d_out, int out_size) {
    const float* x = (const float*)d_in[0];      // [N, 64] fp32
    const float* c = (const float*)d_in[1];      // [512, 64] fp32
    float* out = (float*)d_out;                  // [N, 512] fp32
    int N = in_sizes[0] / D;

    cudaFuncSetAttribute(cluster_q_kernel,
                         cudaFuncAttributeMaxDynamicSharedMemorySize, SMEM_TOTAL);
    cluster_q_kernel<<<N / (TILE_ROWS * ROW_TILES), THREADS, SMEM_TOTAL>>>(x, c, out);
}